// round 4
// baseline (speedup 1.0000x reference)
#include <cuda_runtime.h>

// Dense 3x3 conv, N=32, Cin=Cout=32, H=W=224, stride 1, pad 1, fp32 + bias.
// Round 4: 1024-thread CTA (8 warps/SMSP) on the same 16x32 tile; per-thread
// 4 c_out x 4 px. Same FFMA2 pipe demand, 2x warps for latency hiding.

#define CIN   32
#define COUT  32
#define HH    224
#define WW    224
#define TILE_H 16
#define TILE_W 32
#define SROWS  18
#define SCOLS  34
#define SSTRIDE 35           // odd stride: 3*ty + 4*wg + c mod 32 conflict-free
#define X_SMEM (CIN * SROWS * SSTRIDE)   // 20160 floats (78.75 KB)
#define W_SMEM (CIN * 9 * COUT)          // transposed [ci][k][co]
#define SMEM_FLOATS (X_SMEM + W_SMEM + COUT)
#define NT 1024

typedef unsigned long long ull;

__device__ __forceinline__ ull pack2(float lo, float hi) {
    ull r;
    asm("mov.b64 %0, {%1, %2};" : "=l"(r) : "f"(lo), "f"(hi));
    return r;
}
__device__ __forceinline__ void unpack2(ull v, float& lo, float& hi) {
    asm("mov.b64 {%0, %1}, %2;" : "=f"(lo), "=f"(hi) : "l"(v));
}
__device__ __forceinline__ void fma2(ull& acc, ull a, ull b) {
    asm("fma.rn.f32x2 %0, %1, %2, %0;" : "+l"(acc) : "l"(a), "l"(b));
}

__global__ __launch_bounds__(NT, 1)
void conv3x3_f32x2_kernel(const float* __restrict__ x,
                          const float* __restrict__ wgt,
                          const float* __restrict__ bias,
                          float* __restrict__ out) {
    extern __shared__ float smem[];
    float* sX = smem;                 // [ci][SROWS][SSTRIDE]
    float* sW = smem + X_SMEM;        // transposed: [ci][k(9)][co(32)]
    float* sB = sW + W_SMEM;          // [co]

    const int t  = threadIdx.x;
    const int n  = blockIdx.z;
    const int h0 = blockIdx.y * TILE_H;
    const int w0 = blockIdx.x * TILE_W;

    // Stage weights TRANSPOSED [ci][k][co] so (co, co+1) pairs are contiguous.
    for (int i = t; i < W_SMEM; i += NT) {
        int ci = i / (9 * COUT);
        int r  = i - ci * (9 * COUT);
        int k  = r >> 5;
        int co = r & 31;
        sW[i] = wgt[(co * CIN + ci) * 9 + k];
    }
    if (t < COUT) sB[t] = bias[t];

    // Stage input tile with zero-padded halo.
    const float* xin = x + (size_t)n * CIN * HH * WW;
    for (int idx = t; idx < X_SMEM; idx += NT) {
        int ci  = idx / (SROWS * SSTRIDE);
        int rem = idx - ci * (SROWS * SSTRIDE);
        int r   = rem / SSTRIDE;
        int c   = rem - r * SSTRIDE;
        int gh  = h0 - 1 + r;
        int gw  = w0 - 1 + c;
        float v = 0.0f;
        if (c < SCOLS && (unsigned)gh < HH && (unsigned)gw < WW)
            v = xin[(ci * HH + gh) * WW + gw];
        sX[idx] = v;
    }
    __syncthreads();

    // 1024 threads = 8 co-blocks (4 c_out) x 8 wg (4 px) x 16 ty.
    // co_blk = t>>7: constant per warp -> weight LDS.64 is uniform broadcast.
    const int co_blk = t >> 7;       // 0..7
    const int rem    = t & 127;
    const int wg     = rem & 7;      // 0..7
    const int ty     = rem >> 3;     // 0..15
    const int wbase  = wg * 4;
    const int co0    = co_blk * 4;

    // acc[cp][p]: lo = out[co0+2cp][p], hi = out[co0+2cp+1][p]
    ull acc[2][4];
#pragma unroll
    for (int cp = 0; cp < 2; cp++) {
        ull bb = pack2(sB[co0 + 2 * cp], sB[co0 + 2 * cp + 1]);
#pragma unroll
        for (int p = 0; p < 4; p++) acc[cp][p] = bb;
    }

#pragma unroll 1
    for (int ci = 0; ci < CIN; ci++) {
        const float* xb = sX + ci * (SROWS * SSTRIDE) + ty * SSTRIDE + wbase;
        const float* wp = sW + ci * (9 * COUT) + co0;

#pragma unroll
        for (int dy = 0; dy < 3; dy++) {
            float xv[6];
#pragma unroll
            for (int c = 0; c < 6; c++) xv[c] = xb[dy * SSTRIDE + c];
            ull xd[6];
#pragma unroll
            for (int c = 0; c < 6; c++) xd[c] = pack2(xv[c], xv[c]);

#pragma unroll
            for (int dx = 0; dx < 3; dx++) {
#pragma unroll
                for (int cp = 0; cp < 2; cp++) {
                    ull w2 = *(const ull*)(wp + (dy * 3 + dx) * COUT + 2 * cp);
#pragma unroll
                    for (int p = 0; p < 4; p++)
                        fma2(acc[cp][p], xd[dx + p], w2);
                }
            }
        }
    }

    // Store: 4 consecutive pixels per co row -> STG.128 (16B aligned).
    float* ob = out + ((size_t)n * COUT + co0) * (HH * WW)
                    + (h0 + ty) * WW + (w0 + wbase);
#pragma unroll
    for (int cp = 0; cp < 2; cp++) {
        float r0[4], r1[4];
#pragma unroll
        for (int p = 0; p < 4; p++) unpack2(acc[cp][p], r0[p], r1[p]);
        *(float4*)(ob + (size_t)(2 * cp)     * (HH * WW)) =
            make_float4(r0[0], r0[1], r0[2], r0[3]);
        *(float4*)(ob + (size_t)(2 * cp + 1) * (HH * WW)) =
            make_float4(r1[0], r1[1], r1[2], r1[3]);
    }
}

extern "C" void kernel_launch(void* const* d_in, const int* in_sizes, int n_in,
                              void* d_out, int out_size) {
    const float* x    = (const float*)d_in[0];
    const float* wgt  = (const float*)d_in[1];
    const float* bias = (const float*)d_in[2];
    float* out        = (float*)d_out;

    const int smem_bytes = SMEM_FLOATS * (int)sizeof(float);  // ~115 KB
    cudaFuncSetAttribute(conv3x3_f32x2_kernel,
                         cudaFuncAttributeMaxDynamicSharedMemorySize, smem_bytes);

    dim3 grid(WW / TILE_W, HH / TILE_H, 32);   // (7, 14, 32)
    conv3x3_f32x2_kernel<<<grid, NT, smem_bytes>>>(x, wgt, bias, out);
}

// round 6
// speedup vs baseline: 2.5501x; 2.5501x over previous
#include <cuda_runtime.h>
#include <cstdint>

// Implicit-GEMM 3x3 conv via mma.sync.m16n8k8.tf32 (target-generic tensor path;
// tcgen05 unavailable: harness compiles for plain sm_103).
// N=32, Cin=Cout=32, H=W=224, pad 1, fp32 accum, +bias.
// Persistent CTAs + work stealing over 448 items = (n, 16-row strip).
// Per step: 2 output rows x 224 px = 448 M-pixels, K = 9 taps x 32 ci.

#define CIN 32
#define COUT 32
#define HH 224
#define WW 224
#define NT 512
#define XSTRIDE 36                    // [px][ci] stride: conflict-free A frags
#define XS_PX 226                     // w = -1 .. 224
#define XSLOT (XS_PX * XSTRIDE)       // 8136 u32 per row slot
#define WF_OFF (4 * XSLOT)            // 4-slot ring, then weight fragments
#define BIAS_OFF (WF_OFF + 9 * 1024)
#define WORK_OFF (BIAS_OFF + 32)
#define SMEM_U32 (WORK_OFF + 4)       // 41796 u32 = 167184 B
#define NITEMS (32 * 14)

__device__ int g_work;

__global__ void zero_work_kernel() { g_work = 0; }

static __device__ __forceinline__ uint32_t tf32rna(float v) {
    uint32_t r;
    asm("cvt.rna.tf32.f32 %0, %1;" : "=r"(r) : "f"(v));
    return r;
}

static __device__ __forceinline__ void mma8(float* d, const uint32_t* a,
                                            const uint32_t* b) {
    asm volatile(
        "mma.sync.aligned.m16n8k8.row.col.f32.tf32.tf32.f32 "
        "{%0,%1,%2,%3}, {%4,%5,%6,%7}, {%8,%9}, {%0,%1,%2,%3};"
        : "+f"(d[0]), "+f"(d[1]), "+f"(d[2]), "+f"(d[3])
        : "r"(a[0]), "r"(a[1]), "r"(a[2]), "r"(a[3]), "r"(b[0]), "r"(b[1]));
}

__global__ __launch_bounds__(NT, 1)
void conv3x3_mma_kernel(const float* __restrict__ x,
                        const float* __restrict__ wgt,
                        const float* __restrict__ bias,
                        float* __restrict__ out) {
    extern __shared__ uint32_t sm[];
    uint32_t* xs = sm;                       // 4 row slots, [px][ci] stride 36
    uint32_t* wf = sm + WF_OFF;              // [tap][kc][nc][k*8+n] B-fragments
    float* sB    = (float*)(sm + BIAS_OFF);
    int* swork   = (int*)(sm + WORK_OFF);

    const int tid  = threadIdx.x;
    const int wid  = tid >> 5;
    const int lane = tid & 31;
    const int g    = lane >> 2;   // groupID
    const int tg   = lane & 3;    // thread-in-group

    // Stage weights as ready B fragments: wf val = w[co=nc*8+n][ci=kc*8+k][tap]
    for (int i = tid; i < 9 * 1024; i += NT) {
        int tap = i >> 10, r = i & 1023;
        int kc = r >> 8, nc = (r >> 6) & 3, k = (r >> 3) & 7, nn = r & 7;
        wf[i] = tf32rna(wgt[((nc * 8 + nn) * CIN + (kc * 8 + k)) * 9 + tap]);
    }
    if (tid < COUT) sB[tid] = bias[tid];
    __syncthreads();

    float bv[4][2];
#pragma unroll
    for (int nc = 0; nc < 4; nc++) {
        bv[nc][0] = sB[nc * 8 + 2 * tg];
        bv[nc][1] = sB[nc * 8 + 2 * tg + 1];
    }

    auto load_row = [&](int r, int n) {
        uint32_t* xr = xs + (r & 3) * XSLOT;
        const float* xp = x + (size_t)n * CIN * HH * WW + (size_t)r * WW;
        const bool rok = (unsigned)r < HH;
        for (int i = tid; i < XS_PX * CIN; i += NT) {
            int ci = i / XS_PX;
            int px = i - ci * XS_PX;
            int w  = px - 1;
            float v = 0.0f;
            if (rok && (unsigned)w < WW) v = xp[(size_t)ci * HH * WW + w];
            xr[px * XSTRIDE + ci] = tf32rna(v);
        }
    };

    for (;;) {
        if (tid == 0) *swork = atomicAdd(&g_work, 1);
        __syncthreads();
        const int item = *swork;
        if (item >= NITEMS) break;
        const int n  = item / 14;
        const int h0 = (item - n * 14) * 16;

        load_row(h0 - 1, n);
        load_row(h0,     n);
        load_row(h0 + 1, n);
        load_row(h0 + 2, n);

        for (int j = 0; j < 8; j++) {
            const int R = h0 + 2 * j;
            __syncthreads();                    // loads visible

            if (wid < 14) {                     // 14 compute warps: 2 rows x 224
                const int row = R + (wid >= 7);
                const int px0 = (wid % 7) * 32;

                float C[2][4][4];
#pragma unroll
                for (int mf = 0; mf < 2; mf++)
#pragma unroll
                    for (int nc = 0; nc < 4; nc++)
#pragma unroll
                        for (int q = 0; q < 4; q++) C[mf][nc][q] = 0.0f;

#pragma unroll
                for (int dy = 0; dy < 3; dy++) {
                    const uint32_t* xsl = xs + ((row - 1 + dy) & 3) * XSLOT;
#pragma unroll
                    for (int dx = 0; dx < 3; dx++) {
                        const uint32_t* wt0 = wf + (dy * 3 + dx) * 1024 + tg * 8 + g;
#pragma unroll
                        for (int kc = 0; kc < 4; kc++) {
                            uint32_t b[4][2];
                            const uint32_t* wp = wt0 + kc * 256;
#pragma unroll
                            for (int nc = 0; nc < 4; nc++) {
                                b[nc][0] = wp[nc * 64];
                                b[nc][1] = wp[nc * 64 + 32];
                            }
#pragma unroll
                            for (int mf = 0; mf < 2; mf++) {
                                const uint32_t* ap =
                                    xsl + (px0 + mf * 16 + dx + g) * XSTRIDE + kc * 8 + tg;
                                uint32_t a[4] = { ap[0], ap[8 * XSTRIDE],
                                                  ap[4], ap[8 * XSTRIDE + 4] };
#pragma unroll
                                for (int nc = 0; nc < 4; nc++)
                                    mma8(C[mf][nc], a, b[nc]);
                            }
                        }
                    }
                }

                // Epilogue: D[m][n] -> out[n][co][row][px], add bias.
                float* ob = out + (size_t)n * COUT * HH * WW + (size_t)row * WW;
#pragma unroll
                for (int mf = 0; mf < 2; mf++) {
                    const int px = px0 + mf * 16 + g;
#pragma unroll
                    for (int nc = 0; nc < 4; nc++) {
                        const int co = nc * 8 + 2 * tg;
                        float* o0 = ob + (size_t)co * HH * WW + px;
                        o0[0]           = C[mf][nc][0] + bv[nc][0];
                        o0[HH * WW]     = C[mf][nc][1] + bv[nc][1];
                        o0[8]           = C[mf][nc][2] + bv[nc][0];
                        o0[HH * WW + 8] = C[mf][nc][3] + bv[nc][1];
                    }
                }
            }
            __syncthreads();                    // compute done before slot reuse
            if (j < 7) { load_row(R + 3, n); load_row(R + 4, n); }
        }
    }
}

extern "C" void kernel_launch(void* const* d_in, const int* in_sizes, int n_in,
                              void* d_out, int out_size) {
    const float* x    = (const float*)d_in[0];
    const float* wgt  = (const float*)d_in[1];
    const float* bias = (const float*)d_in[2];
    float* out        = (float*)d_out;

    const int smem_bytes = SMEM_U32 * (int)sizeof(uint32_t);  // ~163 KB
    cudaFuncSetAttribute(conv3x3_mma_kernel,
                         cudaFuncAttributeMaxDynamicSharedMemorySize, smem_bytes);

    int sms = 148;
    cudaDeviceGetAttribute(&sms, cudaDevAttrMultiProcessorCount, 0);
    if (sms < 1) sms = 148;
    if (sms > NITEMS) sms = NITEMS;

    zero_work_kernel<<<1, 1>>>();
    conv3x3_mma_kernel<<<sms, NT, smem_bytes>>>(x, wgt, bias, out);
}

// round 9
// speedup vs baseline: 3.4468x; 1.3516x over previous
#include <cuda_runtime.h>
#include <cstdint>

// Implicit-GEMM 3x3 conv via mma.sync.m16n8k8.tf32, cp.async-pipelined.
// x staged raw fp32 [ci][px] (HW tf32 truncation in MMA); weights rna-cvt once.
// Persistent CTAs + work stealing over 448 items = (n, 16-row strip).
// (Resubmit: two consecutive GPU-acquisition infra failures; never ran.)

#define CIN 32
#define COUT 32
#define HH 224
#define WW 224
#define NT 512
#define XSTRIDE 232                  // words/ci-row: ==8 mod 32 -> A conflict-free
#define XSLOT (CIN * XSTRIDE)        // 7424 words per row slot
#define NSLOT 6
#define WF_OFF (NSLOT * XSLOT)       // 44544
#define BIAS_OFF (WF_OFF + 9 * 1024) // 53760
#define WORK_OFF (BIAS_OFF + 32)
#define SMEM_U32 (WORK_OFF + 4)      // 53796 u32 = 215184 B
#define NITEMS (32 * 14)

__device__ int g_work;
__global__ void zero_work_kernel() { g_work = 0; }

static __device__ __forceinline__ uint32_t smem_u32(const void* p) {
    uint32_t a;
    asm("{ .reg .u64 t; cvta.to.shared.u64 t, %1; cvt.u32.u64 %0, t; }"
        : "=r"(a) : "l"(p));
    return a;
}
static __device__ __forceinline__ uint32_t tf32rna(float v) {
    uint32_t r;
    asm("cvt.rna.tf32.f32 %0, %1;" : "=r"(r) : "f"(v));
    return r;
}
static __device__ __forceinline__ void cp16(uint32_t dst, const void* src) {
    asm volatile("cp.async.ca.shared.global [%0], [%1], 16;"
                 :: "r"(dst), "l"(src) : "memory");
}
static __device__ __forceinline__ void cp_commit() {
    asm volatile("cp.async.commit_group;" ::: "memory");
}
static __device__ __forceinline__ void cp_wait_all() {
    asm volatile("cp.async.wait_group 0;" ::: "memory");
}
static __device__ __forceinline__ void mma8(float* d, const uint32_t* a,
                                            uint32_t b0, uint32_t b1) {
    asm volatile(
        "mma.sync.aligned.m16n8k8.row.col.f32.tf32.tf32.f32 "
        "{%0,%1,%2,%3}, {%4,%5,%6,%7}, {%8,%9}, {%0,%1,%2,%3};"
        : "+f"(d[0]), "+f"(d[1]), "+f"(d[2]), "+f"(d[3])
        : "r"(a[0]), "r"(a[1]), "r"(a[2]), "r"(a[3]), "r"(b0), "r"(b1));
}

__global__ __launch_bounds__(NT, 1)
void conv3x3_mma_kernel(const float* __restrict__ x,
                        const float* __restrict__ wgt,
                        const float* __restrict__ bias,
                        float* __restrict__ out) {
    extern __shared__ uint32_t sm[];
    uint32_t* wf = sm + WF_OFF;
    float* sB    = (float*)(sm + BIAS_OFF);
    int* swork   = (int*)(sm + WORK_OFF);
    const uint32_t sb = smem_u32(sm);

    const int tid  = threadIdx.x;
    const int wid  = tid >> 5;
    const int lane = tid & 31;
    const int g    = lane >> 2;
    const int tg   = lane & 3;

    // Zero whole x region once (halo words stay 0 forever).
    for (int i = tid; i < WF_OFF; i += NT) sm[i] = 0u;

    // Weight B-fragments, interleaved (k, k+4) pairs for LDS.64:
    // word = tap*1024 + kc*256 + nc*64 + (k&3)*16 + n*2 + (k>>2)
    for (int i = tid; i < 9 * 1024; i += NT) {
        int tap = i >> 10, kc = (i >> 8) & 3, nc = (i >> 6) & 3;
        int kl = (i >> 4) & 3, n = (i >> 1) & 7, kh = i & 1;
        int k = kh * 4 + kl;
        wf[i] = tf32rna(wgt[((nc * 8 + n) * CIN + (kc * 8 + k)) * 9 + tap]);
    }
    if (tid < COUT) sB[tid] = bias[tid];
    __syncthreads();

    float bv[4][2];
#pragma unroll
    for (int nc = 0; nc < 4; nc++) {
        bv[nc][0] = sB[nc * 8 + 2 * tg];
        bv[nc][1] = sB[nc * 8 + 2 * tg + 1];
    }

    // Row loader: slot word (ci*232 + 4 + w) = x[ci][r][w]; halo words 3,228 = 0.
    auto load_row = [&](int r, int n) {
        int slot = (r + NSLOT) % NSLOT;
        if ((unsigned)r < HH) {
            const float* xp = x + (size_t)n * CIN * HH * WW + (size_t)r * WW;
            uint32_t db = sb + (uint32_t)(slot * XSLOT * 4);
            for (int i = tid; i < CIN * 56; i += NT) {
                int ci = i / 56, ch = i - ci * 56;
                cp16(db + (uint32_t)((ci * XSTRIDE + 4 + ch * 4) * 4),
                     xp + (size_t)ci * HH * WW + ch * 4);
            }
        } else {
            uint32_t* sl = sm + slot * XSLOT;
            for (int i = tid; i < XSLOT; i += NT) sl[i] = 0u;
        }
    };

    for (;;) {
        if (tid == 0) *swork = atomicAdd(&g_work, 1);
        __syncthreads();
        const int item = *swork;
        if (item >= NITEMS) break;
        const int n  = item / 14;
        const int h0 = (item - n * 14) * 16;

        load_row(h0 - 1, n); load_row(h0, n);
        load_row(h0 + 1, n); load_row(h0 + 2, n);
        cp_commit();

        for (int j = 0; j < 8; j++) {
            const int R = h0 + 2 * j;
            cp_wait_all();
            __syncthreads();
            if (j < 7) {                         // async: overlaps compute below
                load_row(R + 3, n); load_row(R + 4, n);
                cp_commit();
            }

            if (wid < 14) {
                const int row = R + (wid >= 7);
                const int px0 = (wid % 7) * 32;

                float C[2][4][4];
#pragma unroll
                for (int mf = 0; mf < 2; mf++)
#pragma unroll
                    for (int nc = 0; nc < 4; nc++)
#pragma unroll
                        for (int q = 0; q < 4; q++) C[mf][nc][q] = 0.0f;

#pragma unroll
                for (int dy = 0; dy < 3; dy++) {
                    const uint32_t* xsl = sm + ((row - 1 + dy + NSLOT) % NSLOT) * XSLOT;
#pragma unroll
                    for (int dx = 0; dx < 3; dx++) {
#pragma unroll
                        for (int kc = 0; kc < 4; kc++) {
                            const uint64_t* wp64 = (const uint64_t*)
                                (wf + ((dy * 3 + dx) << 10) + (kc << 8)) + tg * 8 + g;
                            uint32_t b[4][2];
#pragma unroll
                            for (int nc = 0; nc < 4; nc++) {
                                uint64_t v = wp64[nc * 32];
                                b[nc][0] = (uint32_t)v;
                                b[nc][1] = (uint32_t)(v >> 32);
                            }
#pragma unroll
                            for (int mf = 0; mf < 2; mf++) {
                                const uint32_t* ap = xsl + (kc * 8 + tg) * XSTRIDE
                                                   + 3 + px0 + mf * 16 + dx + g;
                                uint32_t a[4] = { ap[0], ap[8],
                                                  ap[4 * XSTRIDE], ap[4 * XSTRIDE + 8] };
#pragma unroll
                                for (int nc = 0; nc < 4; nc++)
                                    mma8(C[mf][nc], a, b[nc][0], b[nc][1]);
                            }
                        }
                    }
                }

                float* ob = out + (size_t)n * COUT * HH * WW + (size_t)row * WW;
#pragma unroll
                for (int mf = 0; mf < 2; mf++) {
                    const int px = px0 + mf * 16 + g;
#pragma unroll
                    for (int nc = 0; nc < 4; nc++) {
                        const int co = nc * 8 + 2 * tg;
                        float* o0 = ob + (size_t)co * HH * WW + px;
                        o0[0]           = C[mf][nc][0] + bv[nc][0];
                        o0[HH * WW]     = C[mf][nc][1] + bv[nc][1];
                        o0[8]           = C[mf][nc][2] + bv[nc][0];
                        o0[HH * WW + 8] = C[mf][nc][3] + bv[nc][1];
                    }
                }
            }
        }
        __syncthreads();   // last compute done before next item's loads
    }
}

extern "C" void kernel_launch(void* const* d_in, const int* in_sizes, int n_in,
                              void* d_out, int out_size) {
    const float* x    = (const float*)d_in[0];
    const float* wgt  = (const float*)d_in[1];
    const float* bias = (const float*)d_in[2];
    float* out        = (float*)d_out;

    const int smem_bytes = SMEM_U32 * (int)sizeof(uint32_t);  // ~210 KB
    cudaFuncSetAttribute(conv3x3_mma_kernel,
                         cudaFuncAttributeMaxDynamicSharedMemorySize, smem_bytes);

    int sms = 148;
    cudaDeviceGetAttribute(&sms, cudaDevAttrMultiProcessorCount, 0);
    if (sms < 1) sms = 148;
    if (sms > NITEMS) sms = NITEMS;

    zero_work_kernel<<<1, 1>>>();
    conv3x3_mma_kernel<<<sms, NT, smem_bytes>>>(x, wgt, bias, out);
}

// round 10
// speedup vs baseline: 3.6919x; 1.0711x over previous
#include <cuda_runtime.h>
#include <cstdint>

// Implicit-GEMM 3x3 conv via mma.sync.m16n8k8.tf32.
// Round: 2-row x 32-px x 32-co warp tile exploiting conv row/dy slot sharing
// (4 A-slot fragments feed 6 (row,dy) mma pairs; B shared across both rows):
// 42 B smem per output vs 72 before -> tensor-bound. 8-row work items.

#define CIN 32
#define COUT 32
#define HH 224
#define WW 224
#define NT 512
#define XSTRIDE 232                  // ==8 mod 32 -> A fragments conflict-free
#define XSLOT (CIN * XSTRIDE)        // 7424 words per row slot
#define NSLOT 6
#define WF_OFF (NSLOT * XSLOT)       // 44544
#define BIAS_OFF (WF_OFF + 9 * 1024)
#define WORK_OFF (BIAS_OFF + 32)
#define SMEM_U32 (WORK_OFF + 4)      // ~215 KB
#define NITEMS (32 * 28)             // (n, 8-row strip)

__device__ int g_work;
__global__ void zero_work_kernel() { g_work = 0; }

static __device__ __forceinline__ uint32_t smem_u32(const void* p) {
    uint32_t a;
    asm("{ .reg .u64 t; cvta.to.shared.u64 t, %1; cvt.u32.u64 %0, t; }"
        : "=r"(a) : "l"(p));
    return a;
}
static __device__ __forceinline__ uint32_t tf32rna(float v) {
    uint32_t r;
    asm("cvt.rna.tf32.f32 %0, %1;" : "=r"(r) : "f"(v));
    return r;
}
static __device__ __forceinline__ void cp16(uint32_t dst, const void* src) {
    asm volatile("cp.async.ca.shared.global [%0], [%1], 16;"
                 :: "r"(dst), "l"(src) : "memory");
}
static __device__ __forceinline__ void cp_commit() {
    asm volatile("cp.async.commit_group;" ::: "memory");
}
static __device__ __forceinline__ void cp_wait_all() {
    asm volatile("cp.async.wait_group 0;" ::: "memory");
}
static __device__ __forceinline__ void mma8(float* d, const uint32_t* a,
                                            uint32_t b0, uint32_t b1) {
    asm volatile(
        "mma.sync.aligned.m16n8k8.row.col.f32.tf32.tf32.f32 "
        "{%0,%1,%2,%3}, {%4,%5,%6,%7}, {%8,%9}, {%0,%1,%2,%3};"
        : "+f"(d[0]), "+f"(d[1]), "+f"(d[2]), "+f"(d[3])
        : "r"(a[0]), "r"(a[1]), "r"(a[2]), "r"(a[3]), "r"(b0), "r"(b1));
}

__global__ __launch_bounds__(NT, 1)
void conv3x3_mma_kernel(const float* __restrict__ x,
                        const float* __restrict__ wgt,
                        const float* __restrict__ bias,
                        float* __restrict__ out) {
    extern __shared__ uint32_t sm[];
    uint32_t* wf = sm + WF_OFF;
    float* sB    = (float*)(sm + BIAS_OFF);
    int* swork   = (int*)(sm + WORK_OFF);
    const uint32_t sb = smem_u32(sm);

    const int tid  = threadIdx.x;
    const int wid  = tid >> 5;
    const int lane = tid & 31;
    const int g    = lane >> 2;
    const int tg   = lane & 3;

    // Zero x region once (halo words 3 and 228 of each ci-row stay 0 forever).
    for (int i = tid; i < WF_OFF; i += NT) sm[i] = 0u;

    // Weight B-fragments, interleaved (k, k+4) pairs for LDS.64:
    // word = tap*1024 + kc*256 + nc*64 + (k&3)*16 + n*2 + (k>>2)
    for (int i = tid; i < 9 * 1024; i += NT) {
        int tap = i >> 10, kc = (i >> 8) & 3, nc = (i >> 6) & 3;
        int kl = (i >> 4) & 3, n = (i >> 1) & 7, kh = i & 1;
        int k = kh * 4 + kl;
        wf[i] = tf32rna(wgt[((nc * 8 + n) * CIN + (kc * 8 + k)) * 9 + tap]);
    }
    if (tid < COUT) sB[tid] = bias[tid];
    __syncthreads();

    float bv[4][2];
#pragma unroll
    for (int nc = 0; nc < 4; nc++) {
        bv[nc][0] = sB[nc * 8 + 2 * tg];
        bv[nc][1] = sB[nc * 8 + 2 * tg + 1];
    }

    // Row loader: slot word (ci*232 + 4 + w) = x[ci][r][w].
    auto load_row = [&](int r, int n) {
        int slot = (r + 2 * NSLOT) % NSLOT;
        if ((unsigned)r < HH) {
            const float* xp = x + (size_t)n * CIN * HH * WW + (size_t)r * WW;
            uint32_t db = sb + (uint32_t)(slot * XSLOT * 4);
            for (int i = tid; i < CIN * 56; i += NT) {
                int ci = i / 56, ch = i - ci * 56;
                cp16(db + (uint32_t)((ci * XSTRIDE + 4 + ch * 4) * 4),
                     xp + (size_t)ci * HH * WW + ch * 4);
            }
        } else {
            uint32_t* sl = sm + slot * XSLOT;
            for (int i = tid; i < XSLOT; i += NT) sl[i] = 0u;
        }
    };

    for (;;) {
        if (tid == 0) *swork = atomicAdd(&g_work, 1);
        __syncthreads();
        const int item = *swork;
        if (item >= NITEMS) break;
        const int n  = item / 28;
        const int h0 = (item - n * 28) * 8;

        for (int r = h0 - 1; r <= h0 + 4; r++) load_row(r, n);
        cp_commit();

        for (int j = 0; j < 2; j++) {
            const int R  = h0 + 4 * j;
            const int rp = R + 2 * (wid >= 7);     // warp's first output row
            const int px0 = (wid % 7) * 32;

            cp_wait_all();
            __syncthreads();

            float C[2][2][4][4];                   // [row][mf][nc][q]
#pragma unroll
            for (int r2 = 0; r2 < 2; r2++)
#pragma unroll
                for (int mf = 0; mf < 2; mf++)
#pragma unroll
                    for (int nc = 0; nc < 4; nc++)
#pragma unroll
                        for (int q = 0; q < 4; q++) C[r2][mf][nc][q] = 0.0f;

            if (wid < 14) {
                // Slot bases for rows rp-1 .. rp+2 (rows rp/rp+1 share dy slots)
                const uint32_t* sl[4];
#pragma unroll
                for (int si = 0; si < 4; si++)
                    sl[si] = sm + ((rp - 1 + si + 2 * NSLOT) % NSLOT) * XSLOT;

#pragma unroll 1
                for (int it = 0; it < 12; it++) {
                    const int dx = it >> 2, kc = it & 3;

                    uint32_t b[4][3][2];           // [nc][dy][k-pair]
#pragma unroll
                    for (int nc = 0; nc < 4; nc++)
#pragma unroll
                        for (int dy = 0; dy < 3; dy++) {
                            const uint64_t* wp64 = (const uint64_t*)
                                (wf + ((dy * 3 + dx) << 10) + (kc << 8) + (nc << 6))
                                + tg * 8 + g;
                            uint64_t v = *wp64;
                            b[nc][dy][0] = (uint32_t)v;
                            b[nc][dy][1] = (uint32_t)(v >> 32);
                        }

#pragma unroll
                    for (int si = 0; si < 4; si++) {
#pragma unroll
                        for (int mf = 0; mf < 2; mf++) {
                            const uint32_t* ap = sl[si] + (kc * 8 + tg) * XSTRIDE
                                               + 3 + px0 + mf * 16 + dx + g;
                            uint32_t a[4] = { ap[0], ap[8],
                                              ap[4 * XSTRIDE], ap[4 * XSTRIDE + 8] };
                            // slot si serves (row0, dy=si) and (row1, dy=si-1)
#pragma unroll
                            for (int nc = 0; nc < 4; nc++) {
                                if (si <= 2)
                                    mma8(C[0][mf][nc], a, b[nc][si][0], b[nc][si][1]);
                                if (si >= 1)
                                    mma8(C[1][mf][nc], a, b[nc][si - 1][0], b[nc][si - 1][1]);
                            }
                        }
                    }
                }
            }
            __syncthreads();                       // slots free

            if (j == 0) {                          // next 4 rows; hidden by epilogue
                for (int r = h0 + 5; r <= h0 + 8; r++) load_row(r, n);
                cp_commit();
            }

            if (wid < 14) {
                float* obase = out + (size_t)n * COUT * HH * WW;
#pragma unroll
                for (int r2 = 0; r2 < 2; r2++) {
#pragma unroll
                    for (int mf = 0; mf < 2; mf++) {
                        const int px = px0 + mf * 16 + g;
#pragma unroll
                        for (int nc = 0; nc < 4; nc++) {
                            const int co = nc * 8 + 2 * tg;
                            float* o0 = obase + (size_t)co * HH * WW
                                      + (size_t)(rp + r2) * WW + px;
                            o0[0]           = C[r2][mf][nc][0] + bv[nc][0];
                            o0[HH * WW]     = C[r2][mf][nc][1] + bv[nc][1];
                            o0[8]           = C[r2][mf][nc][2] + bv[nc][0];
                            o0[HH * WW + 8] = C[r2][mf][nc][3] + bv[nc][1];
                        }
                    }
                }
            }
        }
    }
}

extern "C" void kernel_launch(void* const* d_in, const int* in_sizes, int n_in,
                              void* d_out, int out_size) {
    const float* x    = (const float*)d_in[0];
    const float* wgt  = (const float*)d_in[1];
    const float* bias = (const float*)d_in[2];
    float* out        = (float*)d_out;

    const int smem_bytes = SMEM_U32 * (int)sizeof(uint32_t);  // ~215 KB
    cudaFuncSetAttribute(conv3x3_mma_kernel,
                         cudaFuncAttributeMaxDynamicSharedMemorySize, smem_bytes);

    int sms = 148;
    cudaDeviceGetAttribute(&sms, cudaDevAttrMultiProcessorCount, 0);
    if (sms < 1) sms = 148;
    if (sms > NITEMS) sms = NITEMS;

    zero_work_kernel<<<1, 1>>>();
    conv3x3_mma_kernel<<<sms, NT, smem_bytes>>>(x, wgt, bias, out);
}

// round 17
// speedup vs baseline: 3.9537x; 1.0709x over previous
#include <cuda_runtime.h>
#include <cstdint>

// Implicit-GEMM 3x3 conv via mma.sync.m16n8k8.tf32.
// Round: 2 CTAs/SM (98.4 KB smem, 256 thr) on 112-px strips; 7 compute warps
// of 2-row x 16-px x 32-co with row/dy slot sharing; warp-phase-rotated
// mainloop to break barrier convoys. Work stealing over (n, wstrip, 8-row).
// (Resubmit #6: repeated GPU-broker infra failures; this variant never ran.)

#define CIN 32
#define COUT 32
#define HH 224
#define WW 224
#define NT 256
#define XSTRIDE 120                  // ==24 mod 32 -> A fragments conflict-free
#define XSLOT (CIN * XSTRIDE)        // 3840 words per row slot
#define NSLOT 4
#define WF_OFF (NSLOT * XSLOT)       // 15360
#define BIAS_OFF (WF_OFF + 9 * 1024) // 24576
#define WORK_OFF (BIAS_OFF + 32)
#define SMEM_U32 (WORK_OFF + 4)      // 24612 u32 = 98448 B
#define NITEMS (32 * 2 * 28)         // (n, wstrip, 8-row strip) = 1792

__device__ int g_work;
__global__ void zero_work_kernel() { g_work = 0; }

static __device__ __forceinline__ uint32_t smem_u32(const void* p) {
    uint32_t a;
    asm("{ .reg .u64 t; cvta.to.shared.u64 t, %1; cvt.u32.u64 %0, t; }"
        : "=r"(a) : "l"(p));
    return a;
}
static __device__ __forceinline__ uint32_t tf32rna(float v) {
    uint32_t r;
    asm("cvt.rna.tf32.f32 %0, %1;" : "=r"(r) : "f"(v));
    return r;
}
static __device__ __forceinline__ void cp16(uint32_t dst, const void* src) {
    asm volatile("cp.async.ca.shared.global [%0], [%1], 16;"
                 :: "r"(dst), "l"(src) : "memory");
}
static __device__ __forceinline__ void cp_commit() {
    asm volatile("cp.async.commit_group;" ::: "memory");
}
static __device__ __forceinline__ void cp_wait_all() {
    asm volatile("cp.async.wait_group 0;" ::: "memory");
}
static __device__ __forceinline__ void mma8(float* d, const uint32_t* a,
                                            uint32_t b0, uint32_t b1) {
    asm volatile(
        "mma.sync.aligned.m16n8k8.row.col.f32.tf32.tf32.f32 "
        "{%0,%1,%2,%3}, {%4,%5,%6,%7}, {%8,%9}, {%0,%1,%2,%3};"
        : "+f"(d[0]), "+f"(d[1]), "+f"(d[2]), "+f"(d[3])
        : "r"(a[0]), "r"(a[1]), "r"(a[2]), "r"(a[3]), "r"(b0), "r"(b1));
}

__global__ __launch_bounds__(NT, 2)
void conv3x3_mma_kernel(const float* __restrict__ x,
                        const float* __restrict__ wgt,
                        const float* __restrict__ bias,
                        float* __restrict__ out) {
    extern __shared__ uint32_t sm[];
    uint32_t* wf = sm + WF_OFF;
    float* sB    = (float*)(sm + BIAS_OFF);
    int* swork   = (int*)(sm + WORK_OFF);
    const uint32_t sb = smem_u32(sm);

    const int tid  = threadIdx.x;
    const int wid  = tid >> 5;
    const int lane = tid & 31;
    const int g    = lane >> 2;
    const int tg   = lane & 3;

    // Weight B-fragments, interleaved (k, k+4) pairs for LDS.64:
    // word = tap*1024 + kc*256 + nc*64 + (k&3)*16 + n*2 + (k>>2)
    for (int i = tid; i < 9 * 1024; i += NT) {
        int tap = i >> 10, kc = (i >> 8) & 3, nc = (i >> 6) & 3;
        int kl = (i >> 4) & 3, n = (i >> 1) & 7, kh = i & 1;
        int k = kh * 4 + kl;
        wf[i] = tf32rna(wgt[((nc * 8 + n) * CIN + (kc * 8 + k)) * 9 + tap]);
    }
    if (tid < COUT) sB[tid] = bias[tid];

    float bv[4][2];
#pragma unroll
    for (int nc = 0; nc < 4; nc++) {
        bv[nc][0] = bias[nc * 8 + 2 * tg];
        bv[nc][1] = bias[nc * 8 + 2 * tg + 1];
    }

    // Row loader: slot word (ci*120 + j) = x[ci][r][w0-4+j], j=0..119.
    // Pixel w0-1 lands at word 3; w0+112 at word 116. OOB chunks zeroed.
    auto load_row = [&](int r, const float* xn, int w0) {
        int slot = (r + 8) & 3;
        if ((unsigned)r < HH) {
            const float* xp = xn + (size_t)r * WW;
            uint32_t db = sb + (uint32_t)(slot * XSLOT * 4);
            for (int i = tid; i < CIN * 30; i += NT) {
                int ci = i / 30, c = i - ci * 30;
                int w = w0 - 4 + 4 * c;
                uint32_t dst = db + (uint32_t)((ci * XSTRIDE + 4 * c) * 4);
                if ((unsigned)w < WW)
                    cp16(dst, xp + (size_t)ci * HH * WW + w);
                else
                    *(float4*)(sm + slot * XSLOT + ci * XSTRIDE + 4 * c) =
                        make_float4(0.f, 0.f, 0.f, 0.f);
            }
        } else {
            uint32_t* sl = sm + slot * XSLOT;
            for (int i = tid; i < XSLOT / 4; i += NT)
                ((float4*)sl)[i] = make_float4(0.f, 0.f, 0.f, 0.f);
        }
    };

    const int it0 = 3 * (wid & 3);   // warp phase rotation (convoy breaker)

    for (;;) {
        if (tid == 0) *swork = atomicAdd(&g_work, 1);
        __syncthreads();
        const int item = *swork;
        if (item >= NITEMS) break;
        const int n   = item / 56;
        const int rem = item - n * 56;
        const int w0  = (rem / 28) * 112;
        const int h0  = (rem - (rem / 28) * 28) * 8;
        const float* xn = x + (size_t)n * CIN * HH * WW;

        for (int r = h0 - 1; r <= h0 + 2; r++) load_row(r, xn, w0);
        cp_commit();

        for (int j = 0; j < 4; j++) {
            const int R = h0 + 2 * j;         // output rows R, R+1
            cp_wait_all();
            __syncthreads();

            float C[2][4][4];                 // [row][nc][q]
#pragma unroll
            for (int r2 = 0; r2 < 2; r2++)
#pragma unroll
                for (int nc = 0; nc < 4; nc++)
#pragma unroll
                    for (int q = 0; q < 4; q++) C[r2][nc][q] = 0.0f;

            const int px0 = wid * 16;
            if (wid < 7) {
                const uint32_t* sl[4];        // rows R-1 .. R+2
#pragma unroll
                for (int si = 0; si < 4; si++)
                    sl[si] = sm + ((R - 1 + si + 8) & 3) * XSLOT;

#pragma unroll 1
                for (int it = 0; it < 12; it++) {
                    const int idx = (it + it0) % 12;
                    const int dx = idx >> 2, kc = idx & 3;

                    uint32_t b[4][3][2];      // [nc][dy][k-pair]
#pragma unroll
                    for (int nc = 0; nc < 4; nc++)
#pragma unroll
                        for (int dy = 0; dy < 3; dy++) {
                            const uint64_t* wp64 = (const uint64_t*)
                                (wf + ((dy * 3 + dx) << 10) + (kc << 8) + (nc << 6))
                                + tg * 8 + g;
                            uint64_t v = *wp64;
                            b[nc][dy][0] = (uint32_t)v;
                            b[nc][dy][1] = (uint32_t)(v >> 32);
                        }

#pragma unroll
                    for (int si = 0; si < 4; si++) {
                        const uint32_t* ap = sl[si] + (kc * 8 + tg) * XSTRIDE
                                           + 3 + px0 + dx + g;
                        uint32_t a[4] = { ap[0], ap[8],
                                          ap[4 * XSTRIDE], ap[4 * XSTRIDE + 8] };
                        // slot si serves (row R, dy=si) and (row R+1, dy=si-1)
#pragma unroll
                        for (int nc = 0; nc < 4; nc++) {
                            if (si <= 2)
                                mma8(C[0][nc], a, b[nc][si][0], b[nc][si][1]);
                            if (si >= 1)
                                mma8(C[1][nc], a, b[nc][si - 1][0], b[nc][si - 1][1]);
                        }
                    }
                }
            }
            __syncthreads();                  // slot reads done

            if (j < 3) {                      // next 2 rows; DMA overlaps epilogue
                load_row(R + 3, xn, w0);
                load_row(R + 4, xn, w0);
                cp_commit();
            }

            if (wid < 7) {
                const int px = w0 + px0 + g;
                float* obase = out + (size_t)n * COUT * HH * WW;
#pragma unroll
                for (int r2 = 0; r2 < 2; r2++) {
#pragma unroll
                    for (int nc = 0; nc < 4; nc++) {
                        const int co = nc * 8 + 2 * tg;
                        float* o0 = obase + (size_t)co * HH * WW
                                  + (size_t)(R + r2) * WW + px;
                        o0[0]           = C[r2][nc][0] + bv[nc][0];
                        o0[HH * WW]     = C[r2][nc][1] + bv[nc][1];
                        o0[8]           = C[r2][nc][2] + bv[nc][0];
                        o0[HH * WW + 8] = C[r2][nc][3] + bv[nc][1];
                    }
                }
            }
        }
    }
}

extern "C" void kernel_launch(void* const* d_in, const int* in_sizes, int n_in,
                              void* d_out, int out_size) {
    const float* x    = (const float*)d_in[0];
    const float* wgt  = (const float*)d_in[1];
    const float* bias = (const float*)d_in[2];
    float* out        = (float*)d_out;

    const int smem_bytes = SMEM_U32 * (int)sizeof(uint32_t);  // 98448 B
    cudaFuncSetAttribute(conv3x3_mma_kernel,
                         cudaFuncAttributeMaxDynamicSharedMemorySize, smem_bytes);

    int sms = 148;
    cudaDeviceGetAttribute(&sms, cudaDevAttrMultiProcessorCount, 0);
    if (sms < 1) sms = 148;
    int grid = 2 * sms;
    if (grid > NITEMS) grid = NITEMS;

    zero_work_kernel<<<1, 1>>>();
    conv3x3_mma_kernel<<<grid, NT, smem_bytes>>>(x, wgt, bias, out);
}